// round 2
// baseline (speedup 1.0000x reference)
#include <cuda_runtime.h>
#include <cuda_bf16.h>

#define BOOKS 8
#define NROWS 1024
#define INFEAT 2048
#define OUTF 4096
#define LW 256
#define WORDS 256

// Scratch (device globals; no runtime allocation allowed)
__device__ float g_xn[BOOKS * NROWS * LW];     // normalized x  [b][n][d]
__device__ float g_sn[BOOKS * NROWS * LW];     // normalized s  [b][n][d]
__device__ float g_winv[BOOKS * OUTF];         // 1/max(||w_row||, eps)

// ---------------------------------------------------------------------------
// Kernel B: inverse norms of weight rows. 8 warps/block, 1 row/warp.
// ---------------------------------------------------------------------------
__global__ void wnorm_kernel(const float* __restrict__ weight) {
    int row  = blockIdx.x * 8 + (threadIdx.x >> 5);
    int lane = threadIdx.x & 31;
    const float* w = weight + (size_t)row * LW;
    float ss = 0.f;
#pragma unroll
    for (int j = 0; j < 8; j++) { float v = w[lane + 32 * j]; ss += v * v; }
#pragma unroll
    for (int o = 16; o > 0; o >>= 1) ss += __shfl_xor_sync(0xffffffffu, ss, o);
    if (lane == 0) g_winv[row] = 1.0f / fmaxf(sqrtf(ss), 1e-12f);
}

// ---------------------------------------------------------------------------
// Kernel A: per (book, 16-row tile): xn, logits=x@mlp, softmax -> xc (output 3),
// s = codebooks @ xc^T, sn.  256 threads.
// Dynamic smem layout (floats):
//   xc_s : [16][256]          @ 0      (4096)
//   cb_s : [256][33]          @ 4096   (8448)   transposed codebook chunk
//   s_s  : [16][257]          @ 12544  (4112)
//   x_s  : [16][256]          @ 16656  (4096)
// total 20752 floats = 83008 bytes
// ---------------------------------------------------------------------------
__global__ void bookA_kernel(const float* __restrict__ input,
                             const float* __restrict__ mlp,
                             const float* __restrict__ cb,
                             float* __restrict__ out_xc) {
    extern __shared__ float sm[];
    float* xc_s = sm;
    float* cb_s = sm + 4096;
    float* s_s  = sm + 12544;
    float* x_s  = sm + 16656;
    __shared__ float rinv[16], rmax[16], rsum[16];

    int b = blockIdx.y, n0 = blockIdx.x * 16;
    int t = threadIdx.x, wid = t >> 5, lane = t & 31;

    // load x rows (coalesced)
#pragma unroll
    for (int i = 0; i < 16; i++)
        x_s[i * 256 + t] = input[(size_t)(n0 + i) * INFEAT + b * 256 + t];
    __syncthreads();

    // xn: warp per 2 rows
    for (int i = wid; i < 16; i += 8) {
        float ss = 0.f;
#pragma unroll
        for (int j = 0; j < 8; j++) { float v = x_s[i * 256 + lane + 32 * j]; ss += v * v; }
#pragma unroll
        for (int o = 16; o > 0; o >>= 1) ss += __shfl_xor_sync(0xffffffffu, ss, o);
        if (!lane) rinv[i] = 1.0f / fmaxf(sqrtf(ss), 1e-12f);
    }
    __syncthreads();
#pragma unroll
    for (int i = 0; i < 16; i++)
        g_xn[((b << 10) + (n0 + i)) * 256 + t] = x_s[i * 256 + t] * rinv[i];

    // logits[i][t] = sum_d x[i][d] * mlp[b][d][t]
    float acc[16];
#pragma unroll
    for (int i = 0; i < 16; i++) acc[i] = 0.f;
    const float* mp = mlp + b * 65536 + t;
#pragma unroll 4
    for (int d = 0; d < 256; d++) {
        float m = __ldg(mp + d * 256);
#pragma unroll
        for (int i = 0; i < 16; i++) acc[i] += x_s[i * 256 + d] * m;
    }
    __syncthreads();
#pragma unroll
    for (int i = 0; i < 16; i++) xc_s[i * 256 + t] = acc[i];
    __syncthreads();

    // softmax reductions (warp per 2 rows)
    for (int i = wid; i < 16; i += 8) {
        float m = -3.4e38f;
#pragma unroll
        for (int j = 0; j < 8; j++) m = fmaxf(m, xc_s[i * 256 + lane + 32 * j]);
#pragma unroll
        for (int o = 16; o > 0; o >>= 1) m = fmaxf(m, __shfl_xor_sync(0xffffffffu, m, o));
        float se = 0.f;
#pragma unroll
        for (int j = 0; j < 8; j++) se += expf(xc_s[i * 256 + lane + 32 * j] - m);
#pragma unroll
        for (int o = 16; o > 0; o >>= 1) se += __shfl_xor_sync(0xffffffffu, se, o);
        if (!lane) { rmax[i] = m; rsum[i] = 1.0f / se; }
    }
    __syncthreads();
#pragma unroll
    for (int i = 0; i < 16; i++) {
        float v = expf(acc[i] - rmax[i]) * rsum[i];
        xc_s[i * 256 + t] = v;
        out_xc[(size_t)(n0 + i) * (BOOKS * WORDS) + b * 256 + t] = v;
    }

    // s[i][d] = sum_w cb[b][d][w] * xc[i][w]   (8 chunks of 32 d)
    int i0 = t >> 5, dl = t & 31;
    const float* cbb = cb + b * 65536;
    for (int c = 0; c < 8; c++) {
        __syncthreads();
#pragma unroll
        for (int d2 = 0; d2 < 32; d2++)
            cb_s[t * 33 + d2] = cbb[(c * 32 + d2) * 256 + t];   // transposed, conflict-free
        __syncthreads();
        float s0 = 0.f, s1 = 0.f;
#pragma unroll 4
        for (int w = 0; w < 256; w++) {
            float cv = cb_s[w * 33 + dl];
            s0 += xc_s[i0 * 256 + w] * cv;
            s1 += xc_s[(i0 + 8) * 256 + w] * cv;
        }
        s_s[i0 * 257 + c * 32 + dl]       = s0;
        s_s[(i0 + 8) * 257 + c * 32 + dl] = s1;
    }
    __syncthreads();

    // sn
    for (int i = wid; i < 16; i += 8) {
        float ss = 0.f;
#pragma unroll
        for (int j = 0; j < 8; j++) { float v = s_s[i * 257 + lane + 32 * j]; ss += v * v; }
#pragma unroll
        for (int o = 16; o > 0; o >>= 1) ss += __shfl_xor_sync(0xffffffffu, ss, o);
        if (!lane) rinv[i] = 1.0f / fmaxf(sqrtf(ss), 1e-12f);
    }
    __syncthreads();
#pragma unroll
    for (int i = 0; i < 16; i++)
        g_sn[((b << 10) + (n0 + i)) * 256 + t] = s_s[i * 257 + t] * rinv[i];
}

// ---------------------------------------------------------------------------
// Kernel C: fused dual GEMM. Block tile 128(n) x 128(o), K=256 in chunks of 32.
// 256 threads, 8x8 per thread, TWO accumulators (xn and sn vs same weight tile).
// smem: 3 tiles of [32][132] floats = 50688 bytes.
// ---------------------------------------------------------------------------
__global__ void __launch_bounds__(256, 1)
gemm_kernel(const float* __restrict__ weight,
            const int* __restrict__ label,
            float* __restrict__ out1,
            float* __restrict__ out2) {
    extern __shared__ float sm[];
    float* xs = sm;            // xn tile [k][n]
    float* zs = sm + 4224;     // sn tile [k][n]
    float* ws = sm + 8448;     // w  tile [k][o]

    int b = blockIdx.z, n0 = blockIdx.y * 128, o0 = blockIdx.x * 128;
    int t = threadIdx.x, ty = t >> 4, tx = t & 15;

    const float* xb = g_xn + ((size_t)(b << 10) + n0) * 256;
    const float* sb = g_sn + ((size_t)(b << 10) + n0) * 256;
    const float* wb = weight + ((size_t)b * OUTF + o0) * 256;

    float acc1[8][8], acc2[8][8];
#pragma unroll
    for (int i = 0; i < 8; i++)
#pragma unroll
        for (int j = 0; j < 8; j++) { acc1[i][j] = 0.f; acc2[i][j] = 0.f; }

    int kc = t & 31, r0 = t >> 5;
    for (int k0 = 0; k0 < 256; k0 += 32) {
        __syncthreads();
#pragma unroll
        for (int p = 0; p < 16; p++) {
            int r = r0 + p * 8;
            xs[kc * 132 + r] = xb[r * 256 + k0 + kc];
            zs[kc * 132 + r] = sb[r * 256 + k0 + kc];
            ws[kc * 132 + r] = wb[r * 256 + k0 + kc];
        }
        __syncthreads();
#pragma unroll
        for (int k = 0; k < 32; k++) {
            float4 a0 = *(const float4*)(xs + k * 132 + ty * 8);
            float4 a1 = *(const float4*)(xs + k * 132 + ty * 8 + 4);
            float4 c0 = *(const float4*)(zs + k * 132 + ty * 8);
            float4 c1 = *(const float4*)(zs + k * 132 + ty * 8 + 4);
            float4 w0 = *(const float4*)(ws + k * 132 + tx * 8);
            float4 w1 = *(const float4*)(ws + k * 132 + tx * 8 + 4);
            float av[8] = {a0.x, a0.y, a0.z, a0.w, a1.x, a1.y, a1.z, a1.w};
            float cv[8] = {c0.x, c0.y, c0.z, c0.w, c1.x, c1.y, c1.z, c1.w};
            float wv[8] = {w0.x, w0.y, w0.z, w0.w, w1.x, w1.y, w1.z, w1.w};
#pragma unroll
            for (int i = 0; i < 8; i++)
#pragma unroll
                for (int j = 0; j < 8; j++) {
                    acc1[i][j] += av[i] * wv[j];
                    acc2[i][j] += cv[i] * wv[j];
                }
        }
    }

    // epilogue: cos = dot * winv, clip, margin, scale
    float winv8[8];
#pragma unroll
    for (int j = 0; j < 8; j++) winv8[j] = g_winv[b * OUTF + o0 + tx * 8 + j];

#pragma unroll
    for (int i = 0; i < 8; i++) {
        int n = n0 + ty * 8 + i;
        int lab = label[n];                       // int32! (JAX x64-disabled)
        size_t base = (size_t)n * (BOOKS * OUTF) + (size_t)b * OUTF + o0 + tx * 8;
        float r1[8], r2[8];
#pragma unroll
        for (int j = 0; j < 8; j++) {
            int o = o0 + tx * 8 + j;
            float sub = (lab == o) ? 0.5f : 0.0f;
            float c1 = fminf(fmaxf(acc1[i][j] * winv8[j], -1.f), 1.f);
            float c2 = fminf(fmaxf(acc2[i][j] * winv8[j], -1.f), 1.f);
            r1[j] = 30.f * (c1 - sub);
            r2[j] = 30.f * (c2 - sub);
        }
        *(float4*)(out1 + base)     = make_float4(r1[0], r1[1], r1[2], r1[3]);
        *(float4*)(out1 + base + 4) = make_float4(r1[4], r1[5], r1[6], r1[7]);
        *(float4*)(out2 + base)     = make_float4(r2[0], r2[1], r2[2], r2[3]);
        *(float4*)(out2 + base + 4) = make_float4(r2[4], r2[5], r2[6], r2[7]);
    }
}

// ---------------------------------------------------------------------------
extern "C" void kernel_launch(void* const* d_in, const int* in_sizes, int n_in,
                              void* d_out, int out_size) {
    const float* input  = (const float*)d_in[0];
    const int*   label  = (const int*)d_in[1];     // int32 (JAX default x64 off)
    const float* weight = (const float*)d_in[2];
    const float* mlp    = (const float*)d_in[3];
    const float* cb     = (const float*)d_in[4];

    float* out  = (float*)d_out;
    float* out1 = out;                                  // [1024][8][4096]
    float* out2 = out + (size_t)NROWS * BOOKS * OUTF;   // [1024][8][4096]
    float* out3 = out + (size_t)2 * NROWS * BOOKS * OUTF; // [1024][8][256]

    cudaFuncSetAttribute(bookA_kernel, cudaFuncAttributeMaxDynamicSharedMemorySize, 83008);
    cudaFuncSetAttribute(gemm_kernel,  cudaFuncAttributeMaxDynamicSharedMemorySize, 50688);

    wnorm_kernel<<<(BOOKS * OUTF) / 8, 256>>>(weight);
    bookA_kernel<<<dim3(NROWS / 16, BOOKS), 256, 83008>>>(input, mlp, cb, out3);
    gemm_kernel<<<dim3(OUTF / 128, NROWS / 128, BOOKS), 256, 50688>>>(weight, label, out1, out2);
}

// round 4
// speedup vs baseline: 1.9593x; 1.9593x over previous
#include <cuda_runtime.h>
#include <cuda_bf16.h>
#include <cstdint>

#define BOOKS 8
#define NROWS 1024
#define INFEAT 2048
#define OUTF 4096
#define LW 256
#define WORDS 256

// Scratch (device globals; no runtime allocation allowed)
__device__ __nv_bfloat16 g_xh[BOOKS * NROWS * LW];
__device__ __nv_bfloat16 g_xl[BOOKS * NROWS * LW];
__device__ __nv_bfloat16 g_sh[BOOKS * NROWS * LW];
__device__ __nv_bfloat16 g_sl[BOOKS * NROWS * LW];
__device__ __nv_bfloat16 g_wh[BOOKS * OUTF * LW];
__device__ __nv_bfloat16 g_wl[BOOKS * OUTF * LW];
__device__ float g_winv[BOOKS * OUTF];

// ===========================================================================
// helpers
// ===========================================================================
__device__ __forceinline__ uint32_t smem_u32(const void* p) {
    uint32_t a;
    asm("{ .reg .u64 t; cvta.to.shared.u64 t, %1; cvt.u32.u64 %0, t; }" : "=r"(a) : "l"(p));
    return a;
}
__device__ __forceinline__ void cp16(uint32_t dst, const void* src) {
    asm volatile("cp.async.cg.shared.global [%0], [%1], 16;" :: "r"(dst), "l"(src));
}
__device__ __forceinline__ void cp_commit() { asm volatile("cp.async.commit_group;"); }
__device__ __forceinline__ void cp_wait1()  { asm volatile("cp.async.wait_group 1;"); }
__device__ __forceinline__ void cp_wait0()  { asm volatile("cp.async.wait_group 0;"); }

__device__ __forceinline__ void ldm4(uint32_t* r, uint32_t addr) {
    asm volatile("ldmatrix.sync.aligned.m8n8.x4.shared.b16 {%0,%1,%2,%3}, [%4];"
                 : "=r"(r[0]), "=r"(r[1]), "=r"(r[2]), "=r"(r[3]) : "r"(addr));
}
__device__ __forceinline__ void mma16816(float* d, const uint32_t* a, const uint32_t* b) {
    asm volatile(
        "mma.sync.aligned.m16n8k16.row.col.f32.bf16.bf16.f32 "
        "{%0,%1,%2,%3}, {%4,%5,%6,%7}, {%8,%9}, {%0,%1,%2,%3};"
        : "+f"(d[0]), "+f"(d[1]), "+f"(d[2]), "+f"(d[3])
        : "r"(a[0]), "r"(a[1]), "r"(a[2]), "r"(a[3]), "r"(b[0]), "r"(b[1]));
}
__device__ __forceinline__ void split_bf16(float v, __nv_bfloat16& h, __nv_bfloat16& l) {
    h = __float2bfloat16(v);
    l = __float2bfloat16(v - __bfloat162float(h));
}

// ---------------------------------------------------------------------------
// wnorm: inverse norms of weight rows. 8 warps/block, 1 row/warp.
// ---------------------------------------------------------------------------
__global__ void wnorm_kernel(const float* __restrict__ weight) {
    int row  = blockIdx.x * 8 + (threadIdx.x >> 5);
    int lane = threadIdx.x & 31;
    const float* w = weight + (size_t)row * LW;
    float ss = 0.f;
#pragma unroll
    for (int j = 0; j < 8; j++) { float v = w[lane + 32 * j]; ss += v * v; }
#pragma unroll
    for (int o = 16; o > 0; o >>= 1) ss += __shfl_xor_sync(0xffffffffu, ss, o);
    if (lane == 0) g_winv[row] = 1.0f / fmaxf(sqrtf(ss), 1e-12f);
}

// ---------------------------------------------------------------------------
// wsplit: elementwise hi/lo bf16 split of weight. 4 elems/thread.
// ---------------------------------------------------------------------------
__global__ void wsplit_kernel(const float* __restrict__ weight) {
    size_t i = (size_t)blockIdx.x * 256 + threadIdx.x;   // float4 index
    float4 v = ((const float4*)weight)[i];
    __nv_bfloat16 h0, h1, h2, h3, l0, l1, l2, l3;
    split_bf16(v.x, h0, l0); split_bf16(v.y, h1, l1);
    split_bf16(v.z, h2, l2); split_bf16(v.w, h3, l3);
    ((__nv_bfloat162*)g_wh)[2 * i]     = __nv_bfloat162(h0, h1);
    ((__nv_bfloat162*)g_wh)[2 * i + 1] = __nv_bfloat162(h2, h3);
    ((__nv_bfloat162*)g_wl)[2 * i]     = __nv_bfloat162(l0, l1);
    ((__nv_bfloat162*)g_wl)[2 * i + 1] = __nv_bfloat162(l2, l3);
}

// ---------------------------------------------------------------------------
// bookA: xn, softmax(x@mlp)->xc, s=cb@xc, sn; writes hi/lo bf16 planes.
// ---------------------------------------------------------------------------
__global__ void bookA_kernel(const float* __restrict__ input,
                             const float* __restrict__ mlp,
                             const float* __restrict__ cb,
                             float* __restrict__ out_xc) {
    extern __shared__ float sm[];
    float* xc_s = sm;
    float* cb_s = sm + 4096;
    float* s_s  = sm + 12544;
    float* x_s  = sm + 16656;
    __shared__ float rinv[16], rmax[16], rsum[16];

    int b = blockIdx.y, n0 = blockIdx.x * 16;
    int t = threadIdx.x, wid = t >> 5, lane = t & 31;

#pragma unroll
    for (int i = 0; i < 16; i++)
        x_s[i * 256 + t] = input[(size_t)(n0 + i) * INFEAT + b * 256 + t];
    __syncthreads();

    for (int i = wid; i < 16; i += 8) {
        float ss = 0.f;
#pragma unroll
        for (int j = 0; j < 8; j++) { float v = x_s[i * 256 + lane + 32 * j]; ss += v * v; }
#pragma unroll
        for (int o = 16; o > 0; o >>= 1) ss += __shfl_xor_sync(0xffffffffu, ss, o);
        if (!lane) rinv[i] = 1.0f / fmaxf(sqrtf(ss), 1e-12f);
    }
    __syncthreads();
#pragma unroll
    for (int i = 0; i < 16; i++) {
        float v = x_s[i * 256 + t] * rinv[i];
        __nv_bfloat16 h, l; split_bf16(v, h, l);
        size_t idx = (size_t)((b << 10) + (n0 + i)) * 256 + t;
        g_xh[idx] = h; g_xl[idx] = l;
    }

    float acc[16];
#pragma unroll
    for (int i = 0; i < 16; i++) acc[i] = 0.f;
    const float* mp = mlp + b * 65536 + t;
#pragma unroll 4
    for (int d = 0; d < 256; d++) {
        float m = __ldg(mp + d * 256);
#pragma unroll
        for (int i = 0; i < 16; i++) acc[i] += x_s[i * 256 + d] * m;
    }
    __syncthreads();
#pragma unroll
    for (int i = 0; i < 16; i++) xc_s[i * 256 + t] = acc[i];
    __syncthreads();

    for (int i = wid; i < 16; i += 8) {
        float m = -3.4e38f;
#pragma unroll
        for (int j = 0; j < 8; j++) m = fmaxf(m, xc_s[i * 256 + lane + 32 * j]);
#pragma unroll
        for (int o = 16; o > 0; o >>= 1) m = fmaxf(m, __shfl_xor_sync(0xffffffffu, m, o));
        float se = 0.f;
#pragma unroll
        for (int j = 0; j < 8; j++) se += expf(xc_s[i * 256 + lane + 32 * j] - m);
#pragma unroll
        for (int o = 16; o > 0; o >>= 1) se += __shfl_xor_sync(0xffffffffu, se, o);
        if (!lane) { rmax[i] = m; rsum[i] = 1.0f / se; }
    }
    __syncthreads();
#pragma unroll
    for (int i = 0; i < 16; i++) {
        float v = expf(acc[i] - rmax[i]) * rsum[i];
        xc_s[i * 256 + t] = v;
        out_xc[(size_t)(n0 + i) * (BOOKS * WORDS) + b * 256 + t] = v;
    }

    int i0 = t >> 5, dl = t & 31;
    const float* cbb = cb + b * 65536;
    for (int c = 0; c < 8; c++) {
        __syncthreads();
#pragma unroll
        for (int d2 = 0; d2 < 32; d2++)
            cb_s[t * 33 + d2] = cbb[(c * 32 + d2) * 256 + t];
        __syncthreads();
        float s0 = 0.f, s1 = 0.f;
#pragma unroll 4
        for (int w = 0; w < 256; w++) {
            float cv = cb_s[w * 33 + dl];
            s0 += xc_s[i0 * 256 + w] * cv;
            s1 += xc_s[(i0 + 8) * 256 + w] * cv;
        }
        s_s[i0 * 257 + c * 32 + dl]       = s0;
        s_s[(i0 + 8) * 257 + c * 32 + dl] = s1;
    }
    __syncthreads();

    for (int i = wid; i < 16; i += 8) {
        float ss = 0.f;
#pragma unroll
        for (int j = 0; j < 8; j++) { float v = s_s[i * 257 + lane + 32 * j]; ss += v * v; }
#pragma unroll
        for (int o = 16; o > 0; o >>= 1) ss += __shfl_xor_sync(0xffffffffu, ss, o);
        if (!lane) rinv[i] = 1.0f / fmaxf(sqrtf(ss), 1e-12f);
    }
    __syncthreads();
#pragma unroll
    for (int i = 0; i < 16; i++) {
        float v = s_s[i * 257 + t] * rinv[i];
        __nv_bfloat16 h, l; split_bf16(v, h, l);
        size_t idx = (size_t)((b << 10) + (n0 + i)) * 256 + t;
        g_sh[idx] = h; g_sl[idx] = l;
    }
}

// ---------------------------------------------------------------------------
// Dual GEMM via mma.sync bf16 split-2.
// Block 128(n) x 128(o), BK=32 fp32-k per stage, double buffered.
// Stage layout (bf16, rows padded to 40 elems = 80B):
//   xh xl sh sl wh wl  each [128][40] = 10240 B -> stage 61440 B, x2 = 122880 B
// 8 warps: 2(m) x 4(o) -> warp tile 64 x 32; mma m16n8k16.
// acc1 = xn@w, acc2 = sn@w share B fragments.
// ---------------------------------------------------------------------------
#define TILE_B 10240
#define STAGE_B 61440

__global__ void __launch_bounds__(256, 1)
gemm_mma(const int* __restrict__ label,
         float* __restrict__ out1,
         float* __restrict__ out2) {
    extern __shared__ char smc[];
    __shared__ float winv_s[128];
    uint32_t sb = smem_u32(smc);
    int t = threadIdx.x, wid = t >> 5, lane = t & 31;
    int b = blockIdx.z, n0 = blockIdx.y * 128, o0 = blockIdx.x * 128;

    if (t < 128) winv_s[t] = g_winv[b * OUTF + o0 + t];

    const __nv_bfloat16* pxh = g_xh + (size_t)((b << 10) + n0) * 256;
    const __nv_bfloat16* pxl = g_xl + (size_t)((b << 10) + n0) * 256;
    const __nv_bfloat16* psh = g_sh + (size_t)((b << 10) + n0) * 256;
    const __nv_bfloat16* psl = g_sl + (size_t)((b << 10) + n0) * 256;
    const __nv_bfloat16* pwh = g_wh + ((size_t)b * OUTF + o0) * 256;
    const __nv_bfloat16* pwl = g_wl + ((size_t)b * OUTF + o0) * 256;

    int lrow = t >> 2, lseg = t & 3;          // cp.async addressing
    uint32_t cpo = (uint32_t)(lrow * 80 + lseg * 16);
    int ge0 = lseg * 8;

#define LOAD_STAGE(chunk, buf)                                              \
    {                                                                       \
        uint32_t base_ = sb + (uint32_t)(buf) * STAGE_B;                    \
        int k0_ = (chunk) * 32;                                             \
        _Pragma("unroll")                                                   \
        for (int p_ = 0; p_ < 2; p_++) {                                    \
            int row_ = lrow + p_ * 64;                                      \
            uint32_t off_ = cpo + (uint32_t)(p_ * 64 * 80);                 \
            int g_ = row_ * 256 + k0_ + ge0;                                \
            cp16(base_ + off_,              pxh + g_);                      \
            cp16(base_ + TILE_B + off_,     pxl + g_);                      \
            cp16(base_ + 2 * TILE_B + off_, psh + g_);                      \
            cp16(base_ + 3 * TILE_B + off_, psl + g_);                      \
            cp16(base_ + 4 * TILE_B + off_, pwh + g_);                      \
            cp16(base_ + 5 * TILE_B + off_, pwl + g_);                      \
        }                                                                   \
        cp_commit();                                                        \
    }

    int wm = wid & 1, wo = wid >> 1;
    int m0 = wm * 64, ow0 = wo * 32;

    float acc1[4][4][4], acc2[4][4][4];
#pragma unroll
    for (int mt = 0; mt < 4; mt++)
#pragma unroll
        for (int ot = 0; ot < 4; ot++)
#pragma unroll
            for (int q = 0; q < 4; q++) { acc1[mt][ot][q] = 0.f; acc2[mt][ot][q] = 0.f; }

    // ldmatrix lane-address components
    uint32_t a_row = (uint32_t)(m0 + (lane & 7) + ((lane >> 3) & 1) * 8);
    uint32_t b_row = (uint32_t)(ow0 + (lane & 7) + ((lane >> 4) & 1) * 8);

    LOAD_STAGE(0, 0)
    LOAD_STAGE(1, 1)

    for (int i = 0; i < 8; i++) {
        if (i < 7) cp_wait1(); else cp_wait0();
        __syncthreads();
        uint32_t base = sb + (uint32_t)(i & 1) * STAGE_B;

#pragma unroll
        for (int kk = 0; kk < 32; kk += 16) {
            uint32_t akb = (uint32_t)((kk + ((lane >> 4) & 1) * 8) * 2);
            uint32_t bkb = (uint32_t)((kk + ((lane >> 3) & 1) * 8) * 2);
            uint32_t a_addr = base + a_row * 80 + akb;
            uint32_t b_addr = base + b_row * 80 + bkb;

            uint32_t fxh[4][4], fxl[4][4], fsh[4][4], fsl[4][4];
#pragma unroll
            for (int mt = 0; mt < 4; mt++) {
                uint32_t ao = a_addr + (uint32_t)(mt * 16 * 80);
                ldm4(fxh[mt], ao);
                ldm4(fxl[mt], ao + TILE_B);
                ldm4(fsh[mt], ao + 2 * TILE_B);
                ldm4(fsl[mt], ao + 3 * TILE_B);
            }
            uint32_t fwh[2][4], fwl[2][4];   // pair p covers ot=2p (r0,r1), 2p+1 (r2,r3)
#pragma unroll
            for (int p = 0; p < 2; p++) {
                uint32_t bo = b_addr + (uint32_t)(p * 16 * 80);
                ldm4(fwh[p], bo + 4 * TILE_B);
                ldm4(fwl[p], bo + 5 * TILE_B);
            }
#pragma unroll
            for (int mt = 0; mt < 4; mt++)
#pragma unroll
                for (int ot = 0; ot < 4; ot++) {
                    const uint32_t* bh = &fwh[ot >> 1][(ot & 1) * 2];
                    const uint32_t* bl = &fwl[ot >> 1][(ot & 1) * 2];
                    mma16816(acc1[mt][ot], fxh[mt], bh);
                    mma16816(acc1[mt][ot], fxh[mt], bl);
                    mma16816(acc1[mt][ot], fxl[mt], bh);
                    mma16816(acc2[mt][ot], fsh[mt], bh);
                    mma16816(acc2[mt][ot], fsh[mt], bl);
                    mma16816(acc2[mt][ot], fsl[mt], bh);
                }
        }
        __syncthreads();
        if (i + 2 < 8) LOAD_STAGE(i + 2, i & 1)
    }

    // ---- epilogue
#pragma unroll
    for (int mt = 0; mt < 4; mt++) {
        int r  = n0 + m0 + mt * 16 + (lane >> 2);
        int la = label[r], lb = label[r + 8];
        size_t ro  = (size_t)r * (BOOKS * OUTF) + (size_t)b * OUTF;
        size_t ro8 = ro + (size_t)8 * (BOOKS * OUTF);
#pragma unroll
        for (int ot = 0; ot < 4; ot++) {
            int oc = ow0 + ot * 8 + 2 * (lane & 3);
            int o  = o0 + oc;
            float wi0 = winv_s[oc], wi1 = winv_s[oc + 1];
            float* A = acc1[mt][ot];
            float* C = acc2[mt][ot];
            float v;
            float2 u;
            // out1, row r
            v = fminf(fmaxf(A[0] * wi0, -1.f), 1.f); if (la == o)     v -= .5f; u.x = 30.f * v;
            v = fminf(fmaxf(A[1] * wi1, -1.f), 1.f); if (la == o + 1) v -= .5f; u.y = 30.f * v;
            *(float2*)(out1 + ro + o) = u;
            // out1, row r+8
            v = fminf(fmaxf(A[2] * wi0, -1.f), 1.f); if (lb == o)     v -= .5f; u.x = 30.f * v;
            v = fminf(fmaxf(A[3] * wi1, -1.f), 1.f); if (lb == o + 1) v -= .5f; u.y = 30.f * v;
            *(float2*)(out1 + ro8 + o) = u;
            // out2, row r
            v = fminf(fmaxf(C[0] * wi0, -1.f), 1.f); if (la == o)     v -= .5f; u.x = 30.f * v;
            v = fminf(fmaxf(C[1] * wi1, -1.f), 1.f); if (la == o + 1) v -= .5f; u.y = 30.f * v;
            *(float2*)(out2 + ro + o) = u;
            // out2, row r+8
            v = fminf(fmaxf(C[2] * wi0, -1.f), 1.f); if (lb == o)     v -= .5f; u.x = 30.f * v;
            v = fminf(fmaxf(C[3] * wi1, -1.f), 1.f); if (lb == o + 1) v -= .5f; u.y = 30.f * v;
            *(float2*)(out2 + ro8 + o) = u;
        }
    }
}

// ---------------------------------------------------------------------------
extern "C" void kernel_launch(void* const* d_in, const int* in_sizes, int n_in,
                              void* d_out, int out_size) {
    const float* input  = (const float*)d_in[0];
    const int*   label  = (const int*)d_in[1];     // int32 (JAX default x64 off)
    const float* weight = (const float*)d_in[2];
    const float* mlp    = (const float*)d_in[3];
    const float* cb     = (const float*)d_in[4];

    float* out  = (float*)d_out;
    float* out1 = out;                                    // [1024][8][4096]
    float* out2 = out + (size_t)NROWS * BOOKS * OUTF;     // [1024][8][4096]
    float* out3 = out + (size_t)2 * NROWS * BOOKS * OUTF; // [1024][8][256]

    cudaFuncSetAttribute(bookA_kernel, cudaFuncAttributeMaxDynamicSharedMemorySize, 83008);
    cudaFuncSetAttribute(gemm_mma, cudaFuncAttributeMaxDynamicSharedMemorySize, 2 * STAGE_B);

    wnorm_kernel<<<(BOOKS * OUTF) / 8, 256>>>(weight);
    wsplit_kernel<<<(BOOKS * OUTF * LW) / 4 / 256, 256>>>(weight);
    bookA_kernel<<<dim3(NROWS / 16, BOOKS), 256, 83008>>>(input, mlp, cb, out3);
    gemm_mma<<<dim3(OUTF / 128, NROWS / 128, BOOKS), 256, 2 * STAGE_B>>>(label, out1, out2);
}